// round 13
// baseline (speedup 1.0000x reference)
#include <cuda_runtime.h>
#include <cuda_bf16.h>
#include <math.h>

// ---------------- problem constants ----------------
#define BB    2
#define LL    1024
#define DM    256
#define DI    512
#define DS    16
#define DR    16
#define DCV   4
#define VB    4               // 2 chains (fwd/bwd) x 2 batch, fused
#define MR2   (VB*LL)         // 4096 rows per GEMM
#define NC    32              // scan chunks
#define CH    (LL/NC)         // 32 steps per chunk
#define NXP   64              // x_proj N padded (48 -> 64)

typedef unsigned long long u64;
typedef unsigned int u32;
typedef __nv_bfloat16 bf16;

// ---------------- device scratch (no allocation allowed) ----------------
__device__ __align__(16) bf16 g_a_hi[MR2*DM],  g_a_lo[MR2*DM];    // layer-0 input split
__device__ __align__(16) bf16 g_b_hi[MR2*DM],  g_b_lo[MR2*DM];    // layer-1 input split
__device__ __align__(16) bf16 g_xc_hi[MR2*DI], g_xc_lo[MR2*DI];   // conv+silu output split
__device__ __align__(16) bf16 g_y_hi[MR2*DI],  g_y_lo[MR2*DI];    // scan output split
__device__ __align__(16) float g_xz [MR2*2*DI];   // in_proj output (xc | z) fp32
__device__ __align__(16) float g_dbl[MR2*48];     // x_proj output (dt_raw|B|C)
__device__ __align__(16) float g_dt [MR2*DI];     // softplus(dt)
__device__ __align__(16) float g_P  [VB*DI*NC*DS];
__device__ __align__(16) float g_H  [VB*DI*NC*DS];
__device__ __align__(16) float g_Hi [VB*DI*NC*DS];
// weight splits (4 layers each)
__device__ __align__(16) bf16 g_wi_hi[4*2*DI*DM], g_wi_lo[4*2*DI*DM];  // in_proj  (1024,256)
__device__ __align__(16) bf16 g_wx_hi[4*NXP*DI],  g_wx_lo[4*NXP*DI];   // x_proj   (64,512) padded
__device__ __align__(16) bf16 g_wo_hi[4*DM*DI],   g_wo_lo[4*DM*DI];    // out_proj (256,512)

// ---------------- baseline-PTX helpers (valid on compute_103) ----------------
__device__ __forceinline__ u32 smem_u32(const void* p) {
    u32 a;
    asm("{ .reg .u64 t; cvta.to.shared.u64 t, %1; cvt.u32.u64 %0, t; }" : "=r"(a) : "l"(p));
    return a;
}
__device__ __forceinline__ void ldmx4(u32& r0, u32& r1, u32& r2, u32& r3, u32 addr) {
    asm volatile("ldmatrix.sync.aligned.m8n8.x4.shared.b16 {%0,%1,%2,%3}, [%4];"
        : "=r"(r0), "=r"(r1), "=r"(r2), "=r"(r3) : "r"(addr));
}
__device__ __forceinline__ void ldmx2(u32& r0, u32& r1, u32 addr) {
    asm volatile("ldmatrix.sync.aligned.m8n8.x2.shared.b16 {%0,%1}, [%2];"
        : "=r"(r0), "=r"(r1) : "r"(addr));
}
__device__ __forceinline__ void mma16816(float* c, const u32* a, const u32* b) {
    asm volatile("mma.sync.aligned.m16n8k16.row.col.f32.bf16.bf16.f32 "
        "{%0,%1,%2,%3}, {%4,%5,%6,%7}, {%8,%9}, {%0,%1,%2,%3};"
        : "+f"(c[0]), "+f"(c[1]), "+f"(c[2]), "+f"(c[3])
        : "r"(a[0]), "r"(a[1]), "r"(a[2]), "r"(a[3]), "r"(b[0]), "r"(b[1]));
}
__device__ __forceinline__ void split2(float v, bf16& hi, bf16& lo) {
    hi = __float2bfloat16(v);
    lo = __float2bfloat16(v - __bfloat162float(hi));
}
__device__ __forceinline__ u32 packbf(bf16 a, bf16 b) {
    __nv_bfloat162 t = __halves2bfloat162(a, b);
    return *(u32*)&t;
}

// ---------------- weight split kernels ----------------
__global__ void wsplit_k(const float* __restrict__ src, bf16* __restrict__ hi,
                         bf16* __restrict__ lo, int n)
{
    int i = blockIdx.x*256 + threadIdx.x;
    if (i < n) split2(src[i], hi[i], lo[i]);
}
__global__ void wsplit_pad_k(const float* __restrict__ src)   // x_proj: 4 layers, 48->64 rows, K=512
{
    int i = blockIdx.x*256 + threadIdx.x;   // 4*64*512
    int k = i & (DI-1);
    int n = (i >> 9) & (NXP-1);
    int lay = i >> 15;
    float v = (n < 48) ? src[((size_t)lay*48 + n)*DI + k] : 0.f;
    split2(v, g_wx_hi[i], g_wx_lo[i]);
}

// ---------------- prep: build 4096-row input split (chain1 time-reversed) ----------------
__global__ void prep_k(const float* __restrict__ x)
{
    int idx = blockIdx.x*256 + threadIdx.x;   // MR2*DM
    int m = idx & (DM-1);
    int r = idx >> 8;
    int l = r & (LL-1);
    int b = (r >> 10) & 1;
    int chain = r >> 11;
    int sl = chain ? (LL-1-l) : l;
    split2(x[(size_t)(b*LL + sl)*DM + m], g_a_hi[idx], g_a_lo[idx]);
}

// ---------------- HMMA GEMM with register-prefetch pipeline ----------------
// C[m,n] = sum_k A[m,k]*W[n,k], bf16 hi/lo split (3 products). BN fixed 64.
// Single static smem buffer; next chunk's LDGs issued right after STS-sync so they
// overlap the current chunk's mma issue.
// MODE 0: fp32 store (Nvalid mask). MODE 1: final interleaved/reversed out.
// MODE 2: hi/lo split bf16 store. Rows >= 2048 use (Whi1,Wlo1).
template<int BM, int MODE>
__global__ __launch_bounds__(256)
void gemm_mma(const bf16* __restrict__ Ahi, const bf16* __restrict__ Alo,
              const bf16* __restrict__ Whi0, const bf16* __restrict__ Wlo0,
              const bf16* __restrict__ Whi1, const bf16* __restrict__ Wlo1,
              float* __restrict__ Cf, bf16* __restrict__ Chi, bf16* __restrict__ Clo,
              int K, int ldc, int Nvalid)
{
    constexpr int BN = 64;
    constexpr int MT = (BM + 31)/32;     // m16 tiles per warp (BM=32 -> 1)
    constexpr int ASZ = BM*80;           // bytes per A split (hi or lo)
    constexpr int WSZ = BN*80;
    constexpr int AIT = (BM*4 + 255)/256;
    constexpr int WIT = (BN*4 + 255)/256;

    __shared__ __align__(16) char smA[2*ASZ];   // [hi | lo]
    __shared__ __align__(16) char smW[2*WSZ];   // [hi | lo]
    u32 sa = smem_u32(smA);
    u32 sw = smem_u32(smW);

    int tid  = threadIdx.x;
    int lane = tid & 31;
    int wid  = tid >> 5;
    int wm   = wid & 1;                  // 2 warps in M
    int wn   = wid >> 1;                 // 4 warps in N
    int m0   = blockIdx.y * BM;
    int n0   = blockIdx.x * BN;

    const bf16* __restrict__ Whi = (m0 >= MR2/2) ? Whi1 : Whi0;
    const bf16* __restrict__ Wlo = (m0 >= MR2/2) ? Wlo1 : Wlo0;

    float acc[MT][2][4];
#pragma unroll
    for (int mt = 0; mt < MT; mt++)
#pragma unroll
        for (int nt = 0; nt < 2; nt++)
#pragma unroll
            for (int r = 0; r < 4; r++) acc[mt][nt][r] = 0.f;

    uint4 pah[AIT], pal[AIT], pwh[WIT], pwl[WIT];

    auto prefetch = [&](int kt) {
#pragma unroll
        for (int t = 0; t < AIT; t++) {
            int i = tid + t*256;
            if (i < BM*4) {
                int m = i >> 2, seg = i & 3;
                size_t go = (size_t)(m0 + m)*K + kt + seg*8;
                pah[t] = *(const uint4*)(Ahi + go);
                pal[t] = *(const uint4*)(Alo + go);
            }
        }
#pragma unroll
        for (int t = 0; t < WIT; t++) {
            int i = tid + t*256;
            if (i < BN*4) {
                int n = i >> 2, seg = i & 3;
                size_t go = (size_t)(n0 + n)*K + kt + seg*8;
                pwh[t] = *(const uint4*)(Whi + go);
                pwl[t] = *(const uint4*)(Wlo + go);
            }
        }
    };
    auto commit = [&]() {
#pragma unroll
        for (int t = 0; t < AIT; t++) {
            int i = tid + t*256;
            if (i < BM*4) {
                int m = i >> 2, seg = i & 3;
                int so = m*80 + seg*16;
                *(uint4*)(smA + so)       = pah[t];
                *(uint4*)(smA + ASZ + so) = pal[t];
            }
        }
#pragma unroll
        for (int t = 0; t < WIT; t++) {
            int i = tid + t*256;
            if (i < BN*4) {
                int n = i >> 2, seg = i & 3;
                int so = n*80 + seg*16;
                *(uint4*)(smW + so)       = pwh[t];
                *(uint4*)(smW + WSZ + so) = pwl[t];
            }
        }
    };

    const int NCH = K >> 5;              // 32-wide k chunks
    prefetch(0);

    for (int c = 0; c < NCH; c++) {
        __syncthreads();                 // previous chunk's smem reads done
        commit();
        __syncthreads();
        if (c + 1 < NCH) prefetch((c + 1) << 5);   // LDGs overlap mma below

#pragma unroll
        for (int ksb = 0; ksb < 2; ksb++) {
            int kb = ksb*32;             // byte offset of k16 sub-block
            u32 ah[MT][4], al[MT][4];
#pragma unroll
            for (int mt = 0; mt < MT; mt++) {
                u32 addr = sa + (wm*(BM/2) + mt*16 + (lane & 15))*80 + kb + ((lane >> 4) << 4);
                ldmx4(ah[mt][0], ah[mt][1], ah[mt][2], ah[mt][3], addr);
                ldmx4(al[mt][0], al[mt][1], al[mt][2], al[mt][3], addr + ASZ);
            }
            u32 bh[2][2], bl[2][2];
#pragma unroll
            for (int nt = 0; nt < 2; nt++) {
                u32 addr = sw + (wn*16 + nt*8 + (lane & 7))*80 + kb + (((lane >> 3) & 1) << 4);
                ldmx2(bh[nt][0], bh[nt][1], addr);
                ldmx2(bl[nt][0], bl[nt][1], addr + WSZ);
            }
#pragma unroll
            for (int mt = 0; mt < MT; mt++)
#pragma unroll
                for (int nt = 0; nt < 2; nt++) {
                    mma16816(acc[mt][nt], ah[mt], bh[nt]);
                    mma16816(acc[mt][nt], ah[mt], bl[nt]);
                    mma16816(acc[mt][nt], al[mt], bh[nt]);
                }
        }
    }

    // epilogue: c frag -> (m = lane/4 [+8], n = 2*(lane%4) [+1])
#pragma unroll
    for (int mt = 0; mt < MT; mt++) {
        int mrow = m0 + wm*(BM/2) + mt*16 + (lane >> 2);
#pragma unroll
        for (int nt = 0; nt < 2; nt++) {
            int n = n0 + wn*16 + nt*8 + 2*(lane & 3);
            float* a = acc[mt][nt];
            if constexpr (MODE == 0) {
                if (n < Nvalid) {
                    *(float2*)&Cf[(size_t)mrow*ldc + n]     = make_float2(a[0], a[1]);
                    *(float2*)&Cf[(size_t)(mrow+8)*ldc + n] = make_float2(a[2], a[3]);
                }
            } else if constexpr (MODE == 1) {
#pragma unroll
                for (int rr = 0; rr < 2; rr++) {
                    int m = mrow + rr*8;
                    int chain = m >> 11, bb = (m >> 10) & 1, l = m & (LL-1);
                    int dr = bb*LL + (chain ? (LL-1-l) : l);
                    *(float2*)&Cf[(size_t)dr*ldc + chain*DM + n] = make_float2(a[rr*2], a[rr*2+1]);
                }
            } else {
#pragma unroll
                for (int rr = 0; rr < 2; rr++) {
                    size_t o = (size_t)(mrow + rr*8)*ldc + n;
                    bf16 h0, l0, h1, l1;
                    split2(a[rr*2],   h0, l0);
                    split2(a[rr*2+1], h1, l1);
                    *(u32*)&Chi[o] = packbf(h0, h1);
                    *(u32*)&Clo[o] = packbf(l0, l1);
                }
            }
        }
    }
}

// ---------------- causal depthwise conv (K=4) + silu, vectorized x4, split output --------
__global__ void conv_silu_k(const float* __restrict__ cw0, const float* __restrict__ cw1,
                            const float* __restrict__ cb0, const float* __restrict__ cb1)
{
    int idx = blockIdx.x*256 + threadIdx.x;   // MR2*DI/4
    int d4 = (idx & (DI/4 - 1)) * 4;
    int r  = idx >> 7;                        // 0..4095
    int l  = r & (LL-1);
    int chain = r >> 11;
    const float* cw = chain ? cw1 : cw0;
    const float* cb = chain ? cb1 : cb0;

    float acc[4];
#pragma unroll
    for (int q = 0; q < 4; q++) acc[q] = cb[d4 + q];
#pragma unroll
    for (int k = 0; k < DCV; k++) {
        int ls = l + k - (DCV-1);
        if (ls >= 0) {
            float4 v = *(const float4*)&g_xz[(size_t)(r + k - (DCV-1))*(2*DI) + d4];
            acc[0] = fmaf(v.x, cw[(d4+0)*DCV + k], acc[0]);
            acc[1] = fmaf(v.y, cw[(d4+1)*DCV + k], acc[1]);
            acc[2] = fmaf(v.z, cw[(d4+2)*DCV + k], acc[2]);
            acc[3] = fmaf(v.w, cw[(d4+3)*DCV + k], acc[3]);
        }
    }
    bf16 h[4], lo[4];
#pragma unroll
    for (int q = 0; q < 4; q++) {
        float v = acc[q] * __fdividef(1.f, 1.f + __expf(-acc[q]));
        split2(v, h[q], lo[q]);
    }
    size_t o = (size_t)r*DI + d4;
    *(uint2*)&g_xc_hi[o] = make_uint2(packbf(h[0], h[1]), packbf(h[2], h[3]));
    *(uint2*)&g_xc_lo[o] = make_uint2(packbf(lo[0], lo[1]), packbf(lo[2], lo[3]));
}

// ---------------- scan pass 1: fused dt + per-chunk products/local states ----------------
__global__ __launch_bounds__(128)
void scan1_k(const float* __restrict__ Al0, const float* __restrict__ Al1,
             const float* __restrict__ Wdt0, const float* __restrict__ Wdt1,
             const float* __restrict__ bdt0, const float* __restrict__ bdt1)
{
    __shared__ float Bsm[CH][DS];
    __shared__ float Dsm[CH][DR];
    int tid = threadIdx.x;
    int d = blockIdx.x*128 + tid;
    int c = blockIdx.y;
    int vb = blockIdx.z;
    int chain = vb >> 1;
    int row0 = vb*LL + c*CH;
    const float* Al  = chain ? Al1  : Al0;
    const float* Wdt = chain ? Wdt1 : Wdt0;
    float bdt = (chain ? bdt1 : bdt0)[d];

    for (int i = tid; i < CH*DS; i += 128) {
        int l = i >> 4, s = i & 15;
        Bsm[l][s] = g_dbl[(row0 + l)*48 + DR + s];
        Dsm[l][s] = g_dbl[(row0 + l)*48 + s];
    }
    __syncthreads();

    float Aa[DS], h[DS], P[DS], Wr[DR];
#pragma unroll
    for (int s = 0; s < DS; s++) {
        Aa[s] = -__expf(Al[d*DS + s]);
        h[s] = 0.f; P[s] = 1.f;
    }
#pragma unroll
    for (int j = 0; j < DR; j++) Wr[j] = Wdt[d*DR + j];

    for (int l = 0; l < CH; l++) {
        int row = row0 + l;
        float a0 = bdt;
#pragma unroll
        for (int j = 0; j < DR; j++) a0 = fmaf(Dsm[l][j], Wr[j], a0);
        float dt = (a0 > 20.f) ? a0 : log1pf(__expf(a0));
        g_dt[(size_t)row*DI + d] = dt;
        float xv = __bfloat162float(g_xc_hi[(size_t)row*DI + d])
                 + __bfloat162float(g_xc_lo[(size_t)row*DI + d]);
        float dtx = dt * xv;
#pragma unroll
        for (int s = 0; s < DS; s++) {
            float a = __expf(dt * Aa[s]);
            h[s] = fmaf(a, h[s], dtx * Bsm[l][s]);
            P[s] *= a;
        }
    }
    size_t base = ((size_t)(vb*DI + d)*NC + c)*DS;
#pragma unroll
    for (int s = 0; s < DS; s++) { g_P[base + s] = P[s]; g_H[base + s] = h[s]; }
}

// ---------------- scan pass 2: combine chunk states ----------------
__global__ void scan2_k()
{
    int idx = blockIdx.x*256 + threadIdx.x;   // VB*DI*DS = 32768
    int bd = idx >> 4, s = idx & 15;
    float h = 0.f;
#pragma unroll
    for (int c = 0; c < NC; c++) {
        size_t o = ((size_t)bd*NC + c)*DS + s;
        g_Hi[o] = h;
        h = fmaf(g_P[o], h, g_H[o]);
    }
}

// ---------------- scan pass 3: recompute with init + fused epilogue (split output) --------
__global__ __launch_bounds__(128)
void scan3_k(const float* __restrict__ Al0, const float* __restrict__ Al1,
             const float* __restrict__ Dp0, const float* __restrict__ Dp1)
{
    __shared__ float Bsm[CH][DS];
    __shared__ float Csm[CH][DS];
    int tid = threadIdx.x;
    int d = blockIdx.x*128 + tid;
    int c = blockIdx.y;
    int vb = blockIdx.z;
    int chain = vb >> 1;
    int row0 = vb*LL + c*CH;
    const float* Al = chain ? Al1 : Al0;
    float Dv = (chain ? Dp1 : Dp0)[d];

    for (int i = tid; i < CH*DS; i += 128) {
        int l = i >> 4, s = i & 15;
        Bsm[l][s] = g_dbl[(row0 + l)*48 + DR + s];
        Csm[l][s] = g_dbl[(row0 + l)*48 + DR + DS + s];
    }
    __syncthreads();

    float Aa[DS], h[DS];
    size_t base = ((size_t)(vb*DI + d)*NC + c)*DS;
#pragma unroll
    for (int s = 0; s < DS; s++) {
        Aa[s] = -__expf(Al[d*DS + s]);
        h[s] = g_Hi[base + s];
    }

    for (int l = 0; l < CH; l++) {
        int row = row0 + l;
        size_t o = (size_t)row*DI + d;
        float dt = g_dt[o];
        float xv = __bfloat162float(g_xc_hi[o]) + __bfloat162float(g_xc_lo[o]);
        float zv = g_xz[(size_t)row*(2*DI) + DI + d];
        float dtx = dt * xv;
        float y = 0.f;
#pragma unroll
        for (int s = 0; s < DS; s++) {
            float a = __expf(dt * Aa[s]);
            h[s] = fmaf(a, h[s], dtx * Bsm[l][s]);
            y = fmaf(h[s], Csm[l][s], y);
        }
        y = fmaf(xv, Dv, y);
        float sz = zv * __fdividef(1.f, 1.f + __expf(-zv));
        split2(y * sz, g_y_hi[o], g_y_lo[o]);
    }
}

// ---------------- host orchestration ----------------
extern "C" void kernel_launch(void* const* d_in, const int* in_sizes, int n_in,
                              void* d_out, int out_size)
{
    (void)in_sizes; (void)n_in; (void)out_size;
    const float* x       = (const float*)d_in[0];
    const float* in_proj = (const float*)d_in[1];
    const float* conv_w  = (const float*)d_in[2];
    const float* conv_b  = (const float*)d_in[3];
    const float* x_proj  = (const float*)d_in[4];
    const float* dt_proj = (const float*)d_in[5];
    const float* dt_bias = (const float*)d_in[6];
    const float* A_log   = (const float*)d_in[7];
    const float* Dvec    = (const float*)d_in[8];
    const float* out_proj= (const float*)d_in[9];
    float* out = (float*)d_out;

    float *pXZ, *pDBL;
    bf16 *pAh, *pAl, *pBh, *pBl, *pXh, *pXl, *pYh, *pYl;
    bf16 *pWih, *pWil, *pWxh, *pWxl, *pWoh, *pWol;
    cudaGetSymbolAddress((void**)&pXZ,  g_xz);
    cudaGetSymbolAddress((void**)&pDBL, g_dbl);
    cudaGetSymbolAddress((void**)&pAh,  g_a_hi);  cudaGetSymbolAddress((void**)&pAl,  g_a_lo);
    cudaGetSymbolAddress((void**)&pBh,  g_b_hi);  cudaGetSymbolAddress((void**)&pBl,  g_b_lo);
    cudaGetSymbolAddress((void**)&pXh,  g_xc_hi); cudaGetSymbolAddress((void**)&pXl,  g_xc_lo);
    cudaGetSymbolAddress((void**)&pYh,  g_y_hi);  cudaGetSymbolAddress((void**)&pYl,  g_y_lo);
    cudaGetSymbolAddress((void**)&pWih, g_wi_hi); cudaGetSymbolAddress((void**)&pWil, g_wi_lo);
    cudaGetSymbolAddress((void**)&pWxh, g_wx_hi); cudaGetSymbolAddress((void**)&pWxl, g_wx_lo);
    cudaGetSymbolAddress((void**)&pWoh, g_wo_hi); cudaGetSymbolAddress((void**)&pWol, g_wo_lo);

    // weight splits (cheap, in graph)
    wsplit_k<<<(4*2*DI*DM)/256, 256>>>(in_proj,  pWih, pWil, 4*2*DI*DM);
    wsplit_k<<<(4*DM*DI)/256,  256>>>(out_proj, pWoh, pWol, 4*DM*DI);
    wsplit_pad_k<<<(4*NXP*DI)/256, 256>>>(x_proj);
    prep_k<<<(MR2*DM)/256, 256>>>(x);

    for (int sl = 0; sl < 2; sl++) {
        int i0 = sl, i1 = sl + 2;
        const float* cw0  = conv_w  + (size_t)i0 * DI * DCV;
        const float* cw1  = conv_w  + (size_t)i1 * DI * DCV;
        const float* cb0  = conv_b  + (size_t)i0 * DI;
        const float* cb1  = conv_b  + (size_t)i1 * DI;
        const float* Wdt0 = dt_proj + (size_t)i0 * DI * DR;
        const float* Wdt1 = dt_proj + (size_t)i1 * DI * DR;
        const float* bdt0 = dt_bias + (size_t)i0 * DI;
        const float* bdt1 = dt_bias + (size_t)i1 * DI;
        const float* Al0  = A_log   + (size_t)i0 * DI * DS;
        const float* Al1  = A_log   + (size_t)i1 * DI * DS;
        const float* Dp0  = Dvec    + (size_t)i0 * DI;
        const float* Dp1  = Dvec    + (size_t)i1 * DI;

        const bf16* Ah  = (sl == 0) ? pAh : pBh;
        const bf16* Al_ = (sl == 0) ? pAl : pBl;

        // in_proj: (4096,256)x(1024,256)^T -> g_xz fp32    grid 16x32 = 512
        gemm_mma<128,0><<<dim3((2*DI)/64, MR2/128), 256>>>(
            Ah, Al_,
            pWih + (size_t)i0*2*DI*DM, pWil + (size_t)i0*2*DI*DM,
            pWih + (size_t)i1*2*DI*DM, pWil + (size_t)i1*2*DI*DM,
            pXZ, nullptr, nullptr, DM, 2*DI, 2*DI);
        // conv + silu -> split (x4 vectorized)
        conv_silu_k<<<(MR2*DI/4)/256, 256>>>(cw0, cw1, cb0, cb1);
        // x_proj: (4096,512)x(48,512)^T -> g_dbl fp32      grid 1x128 = 128
        gemm_mma<32,0><<<dim3(1, MR2/32), 256>>>(
            pXh, pXl,
            pWxh + (size_t)i0*NXP*DI, pWxl + (size_t)i0*NXP*DI,
            pWxh + (size_t)i1*NXP*DI, pWxl + (size_t)i1*NXP*DI,
            pDBL, nullptr, nullptr, DI, 48, 48);
        // scan
        scan1_k<<<dim3(DI/128, NC, VB), 128>>>(Al0, Al1, Wdt0, Wdt1, bdt0, bdt1);
        scan2_k<<<(VB*DI*DS)/256, 256>>>();
        scan3_k<<<dim3(DI/128, NC, VB), 128>>>(Al0, Al1, Dp0, Dp1);
        // out_proj: (4096,512)x(256,512)^T                 grid 4x32 = 128
        if (sl == 0) {
            gemm_mma<128,2><<<dim3(DM/64, MR2/128), 256>>>(
                pYh, pYl,
                pWoh + (size_t)i0*DM*DI, pWol + (size_t)i0*DM*DI,
                pWoh + (size_t)i1*DM*DI, pWol + (size_t)i1*DM*DI,
                nullptr, pBh, pBl, DI, DM, DM);
        } else {
            gemm_mma<128,1><<<dim3(DM/64, MR2/128), 256>>>(
                pYh, pYl,
                pWoh + (size_t)i0*DM*DI, pWol + (size_t)i0*DM*DI,
                pWoh + (size_t)i1*DM*DI, pWol + (size_t)i1*DM*DI,
                out, nullptr, nullptr, DI, 2*DM, DM);
        }
    }
}